// round 15
// baseline (speedup 1.0000x reference)
#include <cuda_runtime.h>
#include <cuda_fp16.h>
#include <cuda_bf16.h>
#include <cstdint>

// Problem constants (fixed by the reference)
#define NPTS   100000
#define C_IMG  512
#define C_PT   256
#define BSZ    8
#define IMH    48
#define IMW    160
#define NPIX   (BSZ * IMH * IMW)     // 61440
#define PIXB   (IMH * IMW)           // 7680 pixels per batch

#define TM     64                // pixels per CTA (GEMM M tile)
#define NTILE  (NPIX / TM)       // 960 G tiles
#define NCHUNK 16                // K chunks of 32
#define W_CHUNK_BYTES 16384      // 256 n-rows x 32 k x 2B (swizzled, 64B rows)
#define A_CHUNK_BYTES 4096       // 32 k-rows x 64 pix x 2B (swizzled, 128B rows)

// GEMM smem layout
#define SMG_A 0                               // 2 x 4096
#define SMG_W (2 * A_CHUNK_BYTES)             // 2 x 16384
#define SMEM_GEMM (SMG_W + 2 * W_CHUNK_BYTES) // 40960 B -> 2 CTAs/SM

#define PROJECT_BLOCKS ((NPTS + 255) / 256)   // 391
#define WCONV_BLOCKS   64

// ---------------- scratch (device globals: no allocation allowed) -------------
__device__ __align__(16) char g_Wbf16[C_PT * C_IMG * 2];    // bf16 W, chunked+swizzled
__device__ __align__(16) __half g_G[NPIX * C_PT];           // per-pixel aligned feat, 31.5 MB
__device__ float4 g_w[NPTS];
__device__ int4   g_off[NPTS];
__device__ int    g_tileflag[NTILE];          // 1 = tile referenced (zeroed by blend)

// ---------------- helpers ------------------------------------------------------
__device__ __forceinline__ uint32_t smem_u32(const void* p) {
    uint32_t a;
    asm("{ .reg .u64 t; cvta.to.shared.u64 t, %1; cvt.u32.u64 %0, t; }"
        : "=r"(a) : "l"(p));
    return a;
}

#define LDSM_X4(r0, r1, r2, r3, addr) \
    asm volatile("ldmatrix.sync.aligned.m8n8.x4.shared.b16 {%0,%1,%2,%3}, [%4];" \
                 : "=r"(r0), "=r"(r1), "=r"(r2), "=r"(r3) : "r"(addr))

#define LDSM_X4_T(r0, r1, r2, r3, addr) \
    asm volatile("ldmatrix.sync.aligned.m8n8.x4.trans.shared.b16 {%0,%1,%2,%3}, [%4];" \
                 : "=r"(r0), "=r"(r1), "=r"(r2), "=r"(r3) : "r"(addr))

__device__ __forceinline__ void mma_bf16(float* d, const uint32_t* a,
                                         uint32_t b0, uint32_t b1) {
    asm volatile(
        "mma.sync.aligned.m16n8k16.row.col.f32.bf16.bf16.f32 "
        "{%0,%1,%2,%3}, {%4,%5,%6,%7}, {%8,%9}, {%0,%1,%2,%3};"
        : "+f"(d[0]), "+f"(d[1]), "+f"(d[2]), "+f"(d[3])
        : "r"(a[0]), "r"(a[1]), "r"(a[2]), "r"(a[3]), "r"(b0), "r"(b1));
}

#define CP_ASYNC16(dst, src) \
    asm volatile("cp.async.cg.shared.global [%0], [%1], 16;" \
                 :: "r"(dst), "l"(src) : "memory")
#define CP_COMMIT() asm volatile("cp.async.commit_group;" ::: "memory")
#define CP_WAIT_ALL() asm volatile("cp.async.wait_group 0;" ::: "memory")

// ================== kernel 1: project points + convert W (merged) =============
__global__ void pre_kernel(const float* __restrict__ centers,
                           const int* __restrict__ bidx,
                           const float* __restrict__ P2,
                           const float* __restrict__ R0,
                           const float* __restrict__ Tr,
                           const float* __restrict__ aw) {
    const int t = threadIdx.x;
    if (blockIdx.x < PROJECT_BLOCKS) {
        // cooperative combined-matrix build: M[b] = P2[b] @ R0[b] @ Tr[b] (3x4)
        __shared__ float s_M[BSZ][12];
        if (t < BSZ * 12) {
            int b = t / 12;
            int i = (t % 12) >> 2;   // row 0..2
            int j = t & 3;           // col 0..3
            float s = 0.f;
            #pragma unroll
            for (int k = 0; k < 4; ++k) {
                // A[k][j] = sum_m R0[b][k][m] * Tr[b][m][j]
                float a = 0.f;
                #pragma unroll
                for (int m = 0; m < 4; ++m)
                    a += R0[b*16 + k*4 + m] * Tr[b*16 + m*4 + j];
                s += P2[b*12 + i*4 + k] * a;
            }
            s_M[b][i*4 + j] = s;
        }
        __syncthreads();

        int tid = blockIdx.x * 256 + t;
        if (tid >= NPTS) return;
        int b = bidx[tid];
        const float* M = s_M[b];
        float x = centers[tid * 3 + 0];
        float y = centers[tid * 3 + 1];
        float z = centers[tid * 3 + 2];
        float u  = M[0] * x + M[1] * y + M[2]  * z + M[3];
        float v  = M[4] * x + M[5] * y + M[6]  * z + M[7];
        float zc = M[8] * x + M[9] * y + M[10] * z + M[11];
        float depth = fmaxf(zc, 1e-5f);
        float uu = u / depth;
        float vv = v / depth;
        bool valid = (zc > 0.f) && (uu >= 0.f) && (uu < (float)IMW) &&
                     (vv >= 0.f) && (vv < (float)IMH);
        float x0f = floorf(uu), y0f = floorf(vv);
        float wx1 = uu - x0f, wx0 = 1.f - wx1;
        float wy1 = vv - y0f, wy0 = 1.f - wy1;
        int xi0 = (int)x0f, yi0 = (int)y0f;

        int   xs[4] = {xi0, xi0 + 1, xi0, xi0 + 1};
        int   ys[4] = {yi0, yi0, yi0 + 1, yi0 + 1};
        float ws[4] = {wx0 * wy0, wx1 * wy0, wx0 * wy1, wx1 * wy1};
        float wo[4];
        int   oo[4];
        #pragma unroll
        for (int j = 0; j < 4; ++j) {
            bool inb = (xs[j] >= 0) && (xs[j] <= IMW - 1) &&
                       (ys[j] >= 0) && (ys[j] <= IMH - 1);
            int xc = min(max(xs[j], 0), IMW - 1);
            int yc = min(max(ys[j], 0), IMH - 1);
            oo[j] = ((b * IMH + yc) * IMW + xc) * C_PT;   // offsets into G
            wo[j] = (valid && inb) ? ws[j] : 0.f;   // select, never multiply
        }
        g_w[tid]   = make_float4(wo[0], wo[1], wo[2], wo[3]);
        g_off[tid] = make_int4(oo[0], oo[1], oo[2], oo[3]);
        // mark referenced G tiles (idempotent plain stores; offsets are read
        // by blend_kernel regardless of weight, so flag all four)
        g_tileflag[oo[0] >> 14] = 1;
        g_tileflag[oo[1] >> 14] = 1;
        g_tileflag[oo[2] >> 14] = 1;
        g_tileflag[oo[3] >> 14] = 1;
    } else {
        // W: chunk c (16KB, K=32): n-row 64B = 4 16B-blocks,
        // block kb at byte c*16384 + n*64 + ((kb ^ ((n>>1)&3)) << 4)
        int idx = (blockIdx.x - PROJECT_BLOCKS) * 256 + t;
        int n   = idx >> 6;
        int kbg = idx & 63;
        int c   = kbg >> 2;
        int kb  = kbg & 3;
        const float4* src = (const float4*)&aw[(size_t)n * C_IMG + kbg * 8];
        float4 v0 = src[0];
        float4 v1 = src[1];
        uint32_t u[4];
        __nv_bfloat162 t0 = __float22bfloat162_rn(make_float2(v0.x, v0.y));
        __nv_bfloat162 t1 = __float22bfloat162_rn(make_float2(v0.z, v0.w));
        __nv_bfloat162 t2 = __float22bfloat162_rn(make_float2(v1.x, v1.y));
        __nv_bfloat162 t3 = __float22bfloat162_rn(make_float2(v1.z, v1.w));
        u[0] = *(uint32_t*)&t0; u[1] = *(uint32_t*)&t1;
        u[2] = *(uint32_t*)&t2; u[3] = *(uint32_t*)&t3;
        *(int4*)(g_Wbf16 + c * W_CHUNK_BYTES + n * 64 + ((kb ^ ((n >> 1) & 3)) << 4)) =
            *(int4*)u;
    }
}

// ================== kernel 2: dense pixel GEMM  G = img^T @ W^T ===============
// A = img in native (B,C,H,W) layout, staged fp32->bf16 per chunk, ldmatrix.trans.
// 256 threads = 8 warps, warp grid 2(Mpix) x 4(Nch). Warp tile 32x64.
// CTAs whose 64-pixel tile is never referenced by any point exit immediately.
__global__ void __launch_bounds__(256, 2)
gemm_kernel(const float* __restrict__ img) {
    if (g_tileflag[blockIdx.x] == 0) return;   // uniform early exit

    extern __shared__ char sm[];
    uint32_t smb = smem_u32(sm);

    const int t    = threadIdx.x;
    const int lane = t & 31;
    const int warp = t >> 5;
    const int p0   = blockIdx.x * TM;          // global pixel base
    const int b    = p0 / PIXB;                // batch (tiles never cross)
    const int hw0  = p0 % PIXB;

    // A staging: thread owns k-row kloc (0..31), pixel block px8 (8 px = 16B bf16)
    const int kloc = t >> 3;
    const int px8  = (t & 7) * 8;
    const float* imgb = img + ((size_t)b * C_IMG) * PIXB + hw0 + px8;
    const uint32_t asts = smb + SMG_A + kloc * 128 +
                          ((((unsigned)px8 >> 3) ^ (kloc & 7)) << 4);

    // ---- prologue: stage img chunk 0, prefetch W chunk 0 -----------------------
    {
        float4 v0 = *(const float4*)(imgb + (size_t)kloc * PIXB);
        float4 v1 = *(const float4*)(imgb + (size_t)kloc * PIXB + 4);
        __nv_bfloat162 h0 = __float22bfloat162_rn(make_float2(v0.x, v0.y));
        __nv_bfloat162 h1 = __float22bfloat162_rn(make_float2(v0.z, v0.w));
        __nv_bfloat162 h2 = __float22bfloat162_rn(make_float2(v1.x, v1.y));
        __nv_bfloat162 h3 = __float22bfloat162_rn(make_float2(v1.z, v1.w));
        asm volatile("st.shared.v4.b32 [%0], {%1, %2, %3, %4};"
                     :: "r"(asts), "r"(*(uint32_t*)&h0), "r"(*(uint32_t*)&h1),
                        "r"(*(uint32_t*)&h2), "r"(*(uint32_t*)&h3));
    }
    {
        const char* src = g_Wbf16;
        uint32_t dst = smb + SMG_W;
        #pragma unroll
        for (int j = 0; j < 4; ++j)
            CP_ASYNC16(dst + (t + j * 256) * 16, src + (size_t)(t + j * 256) * 16);
        CP_COMMIT();
    }

    const int wm = warp & 1;    // pixel group (32 rows)
    const int wn = warp >> 1;   // channel group (64 cols)
    float acc[2][8][4];
    #pragma unroll
    for (int i = 0; i < 2; ++i)
        #pragma unroll
        for (int j = 0; j < 8; ++j)
            #pragma unroll
            for (int r = 0; r < 4; ++r) acc[i][j][r] = 0.f;

    // A (trans) lane addressing
    const int krow  = (lane & 7) | ((lane >> 4) << 3);
    const int mhalf = (lane >> 3) & 1;
    const uint32_t ablk0 = ((unsigned)((wm * 32) >> 3) + mhalf) ^ (lane & 7);
    const uint32_t ablk1 = ((unsigned)((wm * 32 + 16) >> 3) + mhalf) ^ (lane & 7);
    const uint32_t abase0 = krow * 128 + (ablk0 << 4);
    const uint32_t abase1 = krow * 128 + (ablk1 << 4);
    // B (W) lane addressing
    const int brow  = wn * 64 + (lane >> 4) * 8 + (lane & 7);
    const int bhalf = (lane >> 3) & 1;

    CP_WAIT_ALL();
    __syncthreads();

    for (int c = 0; c < NCHUNK; ++c) {
        float4 v0, v1;
        if (c + 1 < NCHUNK) {
            // prefetch img chunk c+1 (LDG; consumed after MMA below)
            const float* s = imgb + (size_t)((c + 1) * 32 + kloc) * PIXB;
            v0 = *(const float4*)(s);
            v1 = *(const float4*)(s + 4);
            // prefetch W chunk c+1
            const char* src = g_Wbf16 + (size_t)(c + 1) * W_CHUNK_BYTES;
            uint32_t dst = smb + SMG_W + ((c + 1) & 1) * W_CHUNK_BYTES;
            #pragma unroll
            for (int j = 0; j < 4; ++j)
                CP_ASYNC16(dst + (t + j * 256) * 16, src + (size_t)(t + j * 256) * 16);
            CP_COMMIT();
        }
        const uint32_t abuf = smb + SMG_A + (c & 1) * A_CHUNK_BYTES;
        const uint32_t wbuf = smb + SMG_W + (c & 1) * W_CHUNK_BYTES;

        #pragma unroll
        for (int ks = 0; ks < 2; ++ks) {
            uint32_t a[2][4];
            LDSM_X4_T(a[0][0], a[0][1], a[0][2], a[0][3],
                      abuf + ks * 2048 + abase0);
            LDSM_X4_T(a[1][0], a[1][1], a[1][2], a[1][3],
                      abuf + ks * 2048 + abase1);
            #pragma unroll
            for (int jj = 0; jj < 4; ++jj) {
                uint32_t b0, b1, b2, b3;
                int nrow = brow + jj * 16;
                int kb   = (ks * 2 + bhalf) ^ ((nrow >> 1) & 3);
                LDSM_X4(b0, b1, b2, b3, wbuf + nrow * 64 + (kb << 4));
                mma_bf16(acc[0][2 * jj],     a[0], b0, b1);
                mma_bf16(acc[0][2 * jj + 1], a[0], b2, b3);
                mma_bf16(acc[1][2 * jj],     a[1], b0, b1);
                mma_bf16(acc[1][2 * jj + 1], a[1], b2, b3);
            }
        }

        if (c + 1 < NCHUNK) {
            // convert + store img chunk c+1 into the other A buffer
            __nv_bfloat162 h0 = __float22bfloat162_rn(make_float2(v0.x, v0.y));
            __nv_bfloat162 h1 = __float22bfloat162_rn(make_float2(v0.z, v0.w));
            __nv_bfloat162 h2 = __float22bfloat162_rn(make_float2(v1.x, v1.y));
            __nv_bfloat162 h3 = __float22bfloat162_rn(make_float2(v1.z, v1.w));
            uint32_t dst = asts + (((c + 1) & 1) ? A_CHUNK_BYTES : 0);
            asm volatile("st.shared.v4.b32 [%0], {%1, %2, %3, %4};"
                         :: "r"(dst), "r"(*(uint32_t*)&h0), "r"(*(uint32_t*)&h1),
                            "r"(*(uint32_t*)&h2), "r"(*(uint32_t*)&h3));
        }
        CP_WAIT_ALL();
        __syncthreads();
    }

    // ---- epilogue: G[pixel][col] = acc (fp16) -----------------------------------
    const int cbase = wn * 64 + (lane & 3) * 2;
    const int rbase = p0 + wm * 32 + (lane >> 2);
    #pragma unroll
    for (int i = 0; i < 2; ++i) {
        #pragma unroll
        for (int half = 0; half < 2; ++half) {
            int pix = rbase + i * 16 + half * 8;
            #pragma unroll
            for (int j = 0; j < 8; ++j) {
                int col = cbase + j * 8;
                __half2 h = __floats2half2_rn(acc[i][j][half * 2 + 0],
                                              acc[i][j][half * 2 + 1]);
                *(__half2*)&g_G[(size_t)pix * C_PT + col] = h;
            }
        }
    }
}

// ================== kernel 3: per-point blend + residual ======================
// 1 warp per 2 points; lane owns 8 channels. All independent loads (8 G from
// L2 + 4 point_feat from HBM + 2 bias) issued up front for max MLP. Also
// zeroes tile flags for the next launch.
__global__ void __launch_bounds__(256)
blend_kernel(const float* __restrict__ point_feat,
             const float* __restrict__ align_b,
             float* __restrict__ out) {
    // reset tile flags (blocks 0..3 cover NTILE=960 ints)
    if (blockIdx.x < 4) {
        int i = blockIdx.x * 256 + threadIdx.x;
        if (i < NTILE) g_tileflag[i] = 0;
    }

    const int lane = threadIdx.x & 31;
    const int p    = blockIdx.x * 16 + (threadIdx.x >> 5) * 2;
    const int ch   = lane * 8;

    float4 w0 = g_w[p];
    float4 w1 = g_w[p + 1];
    int4   o0 = g_off[p];
    int4   o1 = g_off[p + 1];

    // ---- issue ALL independent loads first (12 in flight) ---------------------
    uint4 a0 = __ldcg((const uint4*)(g_G + o0.x + ch));
    uint4 a1 = __ldcg((const uint4*)(g_G + o0.y + ch));
    uint4 a2 = __ldcg((const uint4*)(g_G + o0.z + ch));
    uint4 a3 = __ldcg((const uint4*)(g_G + o0.w + ch));
    uint4 b0 = __ldcg((const uint4*)(g_G + o1.x + ch));
    uint4 b1 = __ldcg((const uint4*)(g_G + o1.y + ch));
    uint4 b2 = __ldcg((const uint4*)(g_G + o1.z + ch));
    uint4 b3 = __ldcg((const uint4*)(g_G + o1.w + ch));
    const float4* pf0 = (const float4*)&point_feat[(size_t)p * C_PT + ch];
    const float4* pf1 = (const float4*)&point_feat[(size_t)(p + 1) * C_PT + ch];
    float4 pa0 = __ldcs(pf0);
    float4 pb0 = __ldcs(pf0 + 1);
    float4 pa1 = __ldcs(pf1);
    float4 pb1 = __ldcs(pf1 + 1);
    float4 bias0 = *(const float4*)&align_b[ch];
    float4 bias1 = *(const float4*)&align_b[ch + 4];

    #pragma unroll
    for (int pt = 0; pt < 2; ++pt) {
        float4 w = pt ? w1 : w0;
        uint4 c0 = pt ? b0 : a0;
        uint4 c1 = pt ? b1 : a1;
        uint4 c2 = pt ? b2 : a2;
        uint4 c3 = pt ? b3 : a3;
        float acc[8];
        #pragma unroll
        for (int k = 0; k < 4; ++k) {
            float2 f0 = __half22float2(((const __half2*)&c0)[k]);
            float2 f1 = __half22float2(((const __half2*)&c1)[k]);
            float2 f2 = __half22float2(((const __half2*)&c2)[k]);
            float2 f3 = __half22float2(((const __half2*)&c3)[k]);
            acc[2*k+0] = w.x * f0.x + w.y * f1.x + w.z * f2.x + w.w * f3.x;
            acc[2*k+1] = w.x * f0.y + w.y * f1.y + w.z * f2.y + w.w * f3.y;
        }
        float4 pa = pt ? pa1 : pa0;
        float4 pb = pt ? pb1 : pb0;
        float4* op = (float4*)&out[(size_t)(p + pt) * C_PT + ch];
        float4 r0, r1;
        r0.x = pa.x + bias0.x + acc[0];
        r0.y = pa.y + bias0.y + acc[1];
        r0.z = pa.z + bias0.z + acc[2];
        r0.w = pa.w + bias0.w + acc[3];
        r1.x = pb.x + bias1.x + acc[4];
        r1.y = pb.y + bias1.y + acc[5];
        r1.z = pb.z + bias1.z + acc[6];
        r1.w = pb.w + bias1.w + acc[7];
        __stcs(op, r0);
        __stcs(op + 1, r1);
    }
}

// ================== launcher ==================================================
extern "C" void kernel_launch(void* const* d_in, const int* in_sizes, int n_in,
                              void* d_out, int out_size) {
    const float* point_feat = (const float*)d_in[0];
    const float* centers    = (const float*)d_in[1];
    const float* img        = (const float*)d_in[2];
    const float* P2         = (const float*)d_in[3];
    const float* R0         = (const float*)d_in[4];
    const float* Tr         = (const float*)d_in[5];
    const float* align_w    = (const float*)d_in[6];
    const float* align_b    = (const float*)d_in[7];
    const int*   bidx       = (const int*)d_in[8];
    float* out = (float*)d_out;

    pre_kernel<<<PROJECT_BLOCKS + WCONV_BLOCKS, 256>>>(centers, bidx, P2, R0, Tr,
                                                       align_w);
    cudaFuncSetAttribute(gemm_kernel,
                         cudaFuncAttributeMaxDynamicSharedMemorySize, SMEM_GEMM);
    gemm_kernel<<<NTILE, 256, SMEM_GEMM>>>(img);
    blend_kernel<<<NPTS / 16, 256>>>(point_feat, align_b, out);
}

// round 16
// speedup vs baseline: 1.0480x; 1.0480x over previous
#include <cuda_runtime.h>
#include <cuda_fp16.h>
#include <cuda_bf16.h>
#include <cstdint>

// Problem constants (fixed by the reference)
#define NPTS   100000
#define C_IMG  512
#define C_PT   256
#define BSZ    8
#define IMH    48
#define IMW    160
#define NPIX   (BSZ * IMH * IMW)     // 61440
#define PIXB   (IMH * IMW)           // 7680 pixels per batch

#define TM     64                // pixels per CTA (GEMM M tile)
#define NTILE  (NPIX / TM)       // 960 G tiles
#define NCHUNK 16                // K chunks of 32
#define W_CHUNK_BYTES 16384      // 256 n-rows x 32 k x 2B (swizzled, 64B rows)
#define A_CHUNK_BYTES 4096       // 32 k-rows x 64 pix x 2B (swizzled, 128B rows)

// GEMM smem layout
#define SMG_A 0                               // 2 x 4096
#define SMG_W (2 * A_CHUNK_BYTES)             // 2 x 16384
#define SMEM_GEMM (SMG_W + 2 * W_CHUNK_BYTES) // 40960 B -> 2 CTAs/SM

#define PROJECT_BLOCKS ((NPTS + 255) / 256)   // 391
#define WCONV_BLOCKS   64

// ---------------- scratch (device globals: no allocation allowed) -------------
__device__ __align__(16) char g_Wbf16[C_PT * C_IMG * 2];    // bf16 W, chunked+swizzled
__device__ __align__(16) __half g_G[NPIX * C_PT];           // per-pixel aligned feat, 31.5 MB
__device__ float4 g_w[NPTS];
__device__ int4   g_off[NPTS];
__device__ int    g_tileflag[NTILE];          // 1 = tile referenced (zeroed by blend)

// ---------------- helpers ------------------------------------------------------
__device__ __forceinline__ uint32_t smem_u32(const void* p) {
    uint32_t a;
    asm("{ .reg .u64 t; cvta.to.shared.u64 t, %1; cvt.u32.u64 %0, t; }"
        : "=r"(a) : "l"(p));
    return a;
}

#define LDSM_X4(r0, r1, r2, r3, addr) \
    asm volatile("ldmatrix.sync.aligned.m8n8.x4.shared.b16 {%0,%1,%2,%3}, [%4];" \
                 : "=r"(r0), "=r"(r1), "=r"(r2), "=r"(r3) : "r"(addr))

#define LDSM_X4_T(r0, r1, r2, r3, addr) \
    asm volatile("ldmatrix.sync.aligned.m8n8.x4.trans.shared.b16 {%0,%1,%2,%3}, [%4];" \
                 : "=r"(r0), "=r"(r1), "=r"(r2), "=r"(r3) : "r"(addr))

__device__ __forceinline__ void mma_bf16(float* d, const uint32_t* a,
                                         uint32_t b0, uint32_t b1) {
    asm volatile(
        "mma.sync.aligned.m16n8k16.row.col.f32.bf16.bf16.f32 "
        "{%0,%1,%2,%3}, {%4,%5,%6,%7}, {%8,%9}, {%0,%1,%2,%3};"
        : "+f"(d[0]), "+f"(d[1]), "+f"(d[2]), "+f"(d[3])
        : "r"(a[0]), "r"(a[1]), "r"(a[2]), "r"(a[3]), "r"(b0), "r"(b1));
}

#define CP_ASYNC16(dst, src) \
    asm volatile("cp.async.cg.shared.global [%0], [%1], 16;" \
                 :: "r"(dst), "l"(src) : "memory")
#define CP_COMMIT() asm volatile("cp.async.commit_group;" ::: "memory")
#define CP_WAIT_ALL() asm volatile("cp.async.wait_group 0;" ::: "memory")

// streaming 4B store to global, L2-targeted (bypass L1 allocate)
#define STG_CG32(ptr, val) \
    asm volatile("st.global.cg.b32 [%0], %1;" :: "l"(ptr), "r"(val) : "memory")

// ================== kernel 1: project points + convert W (merged) =============
__global__ void pre_kernel(const float* __restrict__ centers,
                           const int* __restrict__ bidx,
                           const float* __restrict__ P2,
                           const float* __restrict__ R0,
                           const float* __restrict__ Tr,
                           const float* __restrict__ aw) {
    const int t = threadIdx.x;
    if (blockIdx.x < PROJECT_BLOCKS) {
        // cooperative combined-matrix build: M[b] = P2[b] @ R0[b] @ Tr[b] (3x4)
        __shared__ float s_M[BSZ][12];
        if (t < BSZ * 12) {
            int b = t / 12;
            int i = (t % 12) >> 2;   // row 0..2
            int j = t & 3;           // col 0..3
            float s = 0.f;
            #pragma unroll
            for (int k = 0; k < 4; ++k) {
                // A[k][j] = sum_m R0[b][k][m] * Tr[b][m][j]
                float a = 0.f;
                #pragma unroll
                for (int m = 0; m < 4; ++m)
                    a += R0[b*16 + k*4 + m] * Tr[b*16 + m*4 + j];
                s += P2[b*12 + i*4 + k] * a;
            }
            s_M[b][i*4 + j] = s;
        }
        __syncthreads();

        int tid = blockIdx.x * 256 + t;
        if (tid >= NPTS) return;
        int b = bidx[tid];
        const float* M = s_M[b];
        float x = centers[tid * 3 + 0];
        float y = centers[tid * 3 + 1];
        float z = centers[tid * 3 + 2];
        float u  = M[0] * x + M[1] * y + M[2]  * z + M[3];
        float v  = M[4] * x + M[5] * y + M[6]  * z + M[7];
        float zc = M[8] * x + M[9] * y + M[10] * z + M[11];
        float depth = fmaxf(zc, 1e-5f);
        float uu = u / depth;
        float vv = v / depth;
        bool valid = (zc > 0.f) && (uu >= 0.f) && (uu < (float)IMW) &&
                     (vv >= 0.f) && (vv < (float)IMH);
        float x0f = floorf(uu), y0f = floorf(vv);
        float wx1 = uu - x0f, wx0 = 1.f - wx1;
        float wy1 = vv - y0f, wy0 = 1.f - wy1;
        int xi0 = (int)x0f, yi0 = (int)y0f;

        int   xs[4] = {xi0, xi0 + 1, xi0, xi0 + 1};
        int   ys[4] = {yi0, yi0, yi0 + 1, yi0 + 1};
        float ws[4] = {wx0 * wy0, wx1 * wy0, wx0 * wy1, wx1 * wy1};
        float wo[4];
        int   oo[4];
        #pragma unroll
        for (int j = 0; j < 4; ++j) {
            bool inb = (xs[j] >= 0) && (xs[j] <= IMW - 1) &&
                       (ys[j] >= 0) && (ys[j] <= IMH - 1);
            int xc = min(max(xs[j], 0), IMW - 1);
            int yc = min(max(ys[j], 0), IMH - 1);
            oo[j] = ((b * IMH + yc) * IMW + xc) * C_PT;   // offsets into G
            wo[j] = (valid && inb) ? ws[j] : 0.f;   // select, never multiply
        }
        g_w[tid]   = make_float4(wo[0], wo[1], wo[2], wo[3]);
        g_off[tid] = make_int4(oo[0], oo[1], oo[2], oo[3]);
        // mark referenced G tiles (idempotent plain stores; offsets are read
        // by blend_kernel regardless of weight, so flag all four)
        g_tileflag[oo[0] >> 14] = 1;
        g_tileflag[oo[1] >> 14] = 1;
        g_tileflag[oo[2] >> 14] = 1;
        g_tileflag[oo[3] >> 14] = 1;
    } else {
        // W: chunk c (16KB, K=32): n-row 64B = 4 16B-blocks,
        // block kb at byte c*16384 + n*64 + ((kb ^ ((n>>1)&3)) << 4)
        int idx = (blockIdx.x - PROJECT_BLOCKS) * 256 + t;
        int n   = idx >> 6;
        int kbg = idx & 63;
        int c   = kbg >> 2;
        int kb  = kbg & 3;
        const float4* src = (const float4*)&aw[(size_t)n * C_IMG + kbg * 8];
        float4 v0 = src[0];
        float4 v1 = src[1];
        uint32_t u[4];
        __nv_bfloat162 t0 = __float22bfloat162_rn(make_float2(v0.x, v0.y));
        __nv_bfloat162 t1 = __float22bfloat162_rn(make_float2(v0.z, v0.w));
        __nv_bfloat162 t2 = __float22bfloat162_rn(make_float2(v1.x, v1.y));
        __nv_bfloat162 t3 = __float22bfloat162_rn(make_float2(v1.z, v1.w));
        u[0] = *(uint32_t*)&t0; u[1] = *(uint32_t*)&t1;
        u[2] = *(uint32_t*)&t2; u[3] = *(uint32_t*)&t3;
        *(int4*)(g_Wbf16 + c * W_CHUNK_BYTES + n * 64 + ((kb ^ ((n >> 1) & 3)) << 4)) =
            *(int4*)u;
    }
}

// ================== kernel 2: dense pixel GEMM  G = img^T @ W^T ===============
// A = img in native (B,C,H,W) layout, staged fp32->bf16 per chunk, ldmatrix.trans.
// 256 threads = 8 warps, warp grid 2(Mpix) x 4(Nch). Warp tile 32x64.
// CTAs whose 64-pixel tile is never referenced by any point exit immediately.
__global__ void __launch_bounds__(256, 2)
gemm_kernel(const float* __restrict__ img) {
    if (g_tileflag[blockIdx.x] == 0) return;   // uniform early exit

    extern __shared__ char sm[];
    uint32_t smb = smem_u32(sm);

    const int t    = threadIdx.x;
    const int lane = t & 31;
    const int warp = t >> 5;
    const int p0   = blockIdx.x * TM;          // global pixel base
    const int b    = p0 / PIXB;                // batch (tiles never cross)
    const int hw0  = p0 % PIXB;

    // A staging: thread owns k-row kloc (0..31), pixel block px8 (8 px = 16B bf16)
    const int kloc = t >> 3;
    const int px8  = (t & 7) * 8;
    const float* imgb = img + ((size_t)b * C_IMG) * PIXB + hw0 + px8;
    const uint32_t asts = smb + SMG_A + kloc * 128 +
                          ((((unsigned)px8 >> 3) ^ (kloc & 7)) << 4);

    // ---- prologue: stage img chunk 0, prefetch W chunk 0 -----------------------
    {
        float4 v0 = *(const float4*)(imgb + (size_t)kloc * PIXB);
        float4 v1 = *(const float4*)(imgb + (size_t)kloc * PIXB + 4);
        __nv_bfloat162 h0 = __float22bfloat162_rn(make_float2(v0.x, v0.y));
        __nv_bfloat162 h1 = __float22bfloat162_rn(make_float2(v0.z, v0.w));
        __nv_bfloat162 h2 = __float22bfloat162_rn(make_float2(v1.x, v1.y));
        __nv_bfloat162 h3 = __float22bfloat162_rn(make_float2(v1.z, v1.w));
        asm volatile("st.shared.v4.b32 [%0], {%1, %2, %3, %4};"
                     :: "r"(asts), "r"(*(uint32_t*)&h0), "r"(*(uint32_t*)&h1),
                        "r"(*(uint32_t*)&h2), "r"(*(uint32_t*)&h3));
    }
    {
        const char* src = g_Wbf16;
        uint32_t dst = smb + SMG_W;
        #pragma unroll
        for (int j = 0; j < 4; ++j)
            CP_ASYNC16(dst + (t + j * 256) * 16, src + (size_t)(t + j * 256) * 16);
        CP_COMMIT();
    }

    const int wm = warp & 1;    // pixel group (32 rows)
    const int wn = warp >> 1;   // channel group (64 cols)
    float acc[2][8][4];
    #pragma unroll
    for (int i = 0; i < 2; ++i)
        #pragma unroll
        for (int j = 0; j < 8; ++j)
            #pragma unroll
            for (int r = 0; r < 4; ++r) acc[i][j][r] = 0.f;

    // A (trans) lane addressing
    const int krow  = (lane & 7) | ((lane >> 4) << 3);
    const int mhalf = (lane >> 3) & 1;
    const uint32_t ablk0 = ((unsigned)((wm * 32) >> 3) + mhalf) ^ (lane & 7);
    const uint32_t ablk1 = ((unsigned)((wm * 32 + 16) >> 3) + mhalf) ^ (lane & 7);
    const uint32_t abase0 = krow * 128 + (ablk0 << 4);
    const uint32_t abase1 = krow * 128 + (ablk1 << 4);
    // B (W) lane addressing
    const int brow  = wn * 64 + (lane >> 4) * 8 + (lane & 7);
    const int bhalf = (lane >> 3) & 1;

    CP_WAIT_ALL();
    __syncthreads();

    for (int c = 0; c < NCHUNK; ++c) {
        float4 v0, v1;
        if (c + 1 < NCHUNK) {
            // prefetch img chunk c+1 (LDG; consumed after MMA below)
            const float* s = imgb + (size_t)((c + 1) * 32 + kloc) * PIXB;
            v0 = *(const float4*)(s);
            v1 = *(const float4*)(s + 4);
            // prefetch W chunk c+1
            const char* src = g_Wbf16 + (size_t)(c + 1) * W_CHUNK_BYTES;
            uint32_t dst = smb + SMG_W + ((c + 1) & 1) * W_CHUNK_BYTES;
            #pragma unroll
            for (int j = 0; j < 4; ++j)
                CP_ASYNC16(dst + (t + j * 256) * 16, src + (size_t)(t + j * 256) * 16);
            CP_COMMIT();
        }
        const uint32_t abuf = smb + SMG_A + (c & 1) * A_CHUNK_BYTES;
        const uint32_t wbuf = smb + SMG_W + (c & 1) * W_CHUNK_BYTES;

        #pragma unroll
        for (int ks = 0; ks < 2; ++ks) {
            uint32_t a[2][4];
            LDSM_X4_T(a[0][0], a[0][1], a[0][2], a[0][3],
                      abuf + ks * 2048 + abase0);
            LDSM_X4_T(a[1][0], a[1][1], a[1][2], a[1][3],
                      abuf + ks * 2048 + abase1);
            #pragma unroll
            for (int jj = 0; jj < 4; ++jj) {
                uint32_t b0, b1, b2, b3;
                int nrow = brow + jj * 16;
                int kb   = (ks * 2 + bhalf) ^ ((nrow >> 1) & 3);
                LDSM_X4(b0, b1, b2, b3, wbuf + nrow * 64 + (kb << 4));
                mma_bf16(acc[0][2 * jj],     a[0], b0, b1);
                mma_bf16(acc[0][2 * jj + 1], a[0], b2, b3);
                mma_bf16(acc[1][2 * jj],     a[1], b0, b1);
                mma_bf16(acc[1][2 * jj + 1], a[1], b2, b3);
            }
        }

        if (c + 1 < NCHUNK) {
            // convert + store img chunk c+1 into the other A buffer
            __nv_bfloat162 h0 = __float22bfloat162_rn(make_float2(v0.x, v0.y));
            __nv_bfloat162 h1 = __float22bfloat162_rn(make_float2(v0.z, v0.w));
            __nv_bfloat162 h2 = __float22bfloat162_rn(make_float2(v1.x, v1.y));
            __nv_bfloat162 h3 = __float22bfloat162_rn(make_float2(v1.z, v1.w));
            uint32_t dst = asts + (((c + 1) & 1) ? A_CHUNK_BYTES : 0);
            asm volatile("st.shared.v4.b32 [%0], {%1, %2, %3, %4};"
                         :: "r"(dst), "r"(*(uint32_t*)&h0), "r"(*(uint32_t*)&h1),
                            "r"(*(uint32_t*)&h2), "r"(*(uint32_t*)&h3));
        }
        CP_WAIT_ALL();
        __syncthreads();
    }

    // ---- epilogue: G[pixel][col] = acc (fp16, streaming L2 stores) -------------
    const int cbase = wn * 64 + (lane & 3) * 2;
    const int rbase = p0 + wm * 32 + (lane >> 2);
    #pragma unroll
    for (int i = 0; i < 2; ++i) {
        #pragma unroll
        for (int half = 0; half < 2; ++half) {
            int pix = rbase + i * 16 + half * 8;
            #pragma unroll
            for (int j = 0; j < 8; ++j) {
                int col = cbase + j * 8;
                __half2 h = __floats2half2_rn(acc[i][j][half * 2 + 0],
                                              acc[i][j][half * 2 + 1]);
                STG_CG32((uint32_t*)&g_G[(size_t)pix * C_PT + col],
                         *(uint32_t*)&h);
            }
        }
    }
}

// ================== kernel 3: per-point blend + residual ======================
// 1 warp per 2 points; lane owns 8 channels. Also zeroes tile flags for the
// next launch (gemm consumed them earlier in this launch; device globals are
// zero-initialized, so the first call is covered too).
__global__ void __launch_bounds__(256)
blend_kernel(const float* __restrict__ point_feat,
             const float* __restrict__ align_b,
             float* __restrict__ out) {
    // reset tile flags (blocks 0..3 cover NTILE=960 ints)
    if (blockIdx.x < 4) {
        int i = blockIdx.x * 256 + threadIdx.x;
        if (i < NTILE) g_tileflag[i] = 0;
    }

    const int lane = threadIdx.x & 31;
    const int p    = blockIdx.x * 16 + (threadIdx.x >> 5) * 2;
    const int ch   = lane * 8;

    float4 w0 = g_w[p];
    float4 w1 = g_w[p + 1];
    int4   o0 = g_off[p];
    int4   o1 = g_off[p + 1];
    // 8 independent G loads in flight (L2-only; no L1 reuse)
    uint4 a0 = __ldcg((const uint4*)(g_G + o0.x + ch));
    uint4 a1 = __ldcg((const uint4*)(g_G + o0.y + ch));
    uint4 a2 = __ldcg((const uint4*)(g_G + o0.z + ch));
    uint4 a3 = __ldcg((const uint4*)(g_G + o0.w + ch));
    uint4 b0 = __ldcg((const uint4*)(g_G + o1.x + ch));
    uint4 b1 = __ldcg((const uint4*)(g_G + o1.y + ch));
    uint4 b2 = __ldcg((const uint4*)(g_G + o1.z + ch));
    uint4 b3 = __ldcg((const uint4*)(g_G + o1.w + ch));

    float4 bias0 = *(const float4*)&align_b[ch];
    float4 bias1 = *(const float4*)&align_b[ch + 4];

    #pragma unroll
    for (int pt = 0; pt < 2; ++pt) {
        float4 w = pt ? w1 : w0;
        uint4 c0 = pt ? b0 : a0;
        uint4 c1 = pt ? b1 : a1;
        uint4 c2 = pt ? b2 : a2;
        uint4 c3 = pt ? b3 : a3;
        float acc[8];
        #pragma unroll
        for (int k = 0; k < 4; ++k) {
            float2 f0 = __half22float2(((const __half2*)&c0)[k]);
            float2 f1 = __half22float2(((const __half2*)&c1)[k]);
            float2 f2 = __half22float2(((const __half2*)&c2)[k]);
            float2 f3 = __half22float2(((const __half2*)&c3)[k]);
            acc[2*k+0] = w.x * f0.x + w.y * f1.x + w.z * f2.x + w.w * f3.x;
            acc[2*k+1] = w.x * f0.y + w.y * f1.y + w.z * f2.y + w.w * f3.y;
        }
        const int pp = p + pt;
        const float4* pf = (const float4*)&point_feat[(size_t)pp * C_PT + ch];
        float4* op = (float4*)&out[(size_t)pp * C_PT + ch];
        float4 pa = __ldcs(pf);
        float4 pb = __ldcs(pf + 1);
        float4 r0, r1;
        r0.x = pa.x + bias0.x + acc[0];
        r0.y = pa.y + bias0.y + acc[1];
        r0.z = pa.z + bias0.z + acc[2];
        r0.w = pa.w + bias0.w + acc[3];
        r1.x = pb.x + bias1.x + acc[4];
        r1.y = pb.y + bias1.y + acc[5];
        r1.z = pb.z + bias1.z + acc[6];
        r1.w = pb.w + bias1.w + acc[7];
        __stcs(op, r0);
        __stcs(op + 1, r1);
    }
}

// ================== launcher ==================================================
extern "C" void kernel_launch(void* const* d_in, const int* in_sizes, int n_in,
                              void* d_out, int out_size) {
    const float* point_feat = (const float*)d_in[0];
    const float* centers    = (const float*)d_in[1];
    const float* img        = (const float*)d_in[2];
    const float* P2         = (const float*)d_in[3];
    const float* R0         = (const float*)d_in[4];
    const float* Tr         = (const float*)d_in[5];
    const float* align_w    = (const float*)d_in[6];
    const float* align_b    = (const float*)d_in[7];
    const int*   bidx       = (const int*)d_in[8];
    float* out = (float*)d_out;

    pre_kernel<<<PROJECT_BLOCKS + WCONV_BLOCKS, 256>>>(centers, bidx, P2, R0, Tr,
                                                       align_w);
    cudaFuncSetAttribute(gemm_kernel,
                         cudaFuncAttributeMaxDynamicSharedMemorySize, SMEM_GEMM);
    gemm_kernel<<<NTILE, 256, SMEM_GEMM>>>(img);
    blend_kernel<<<NPTS / 16, 256>>>(point_feat, align_b, out);
}

// round 17
// speedup vs baseline: 1.0937x; 1.0436x over previous
#include <cuda_runtime.h>
#include <cuda_fp16.h>
#include <cuda_bf16.h>
#include <cstdint>

// Problem constants (fixed by the reference)
#define NPTS   100000
#define C_IMG  512
#define C_PT   256
#define BSZ    8
#define IMH    48
#define IMW    160
#define NPIX   (BSZ * IMH * IMW)     // 61440
#define PIXB   (IMH * IMW)           // 7680 pixels per batch

#define TM     64                // pixels per CTA (GEMM M tile)
#define NTILE  (NPIX / TM)       // 960 G tiles
#define NCHUNK 8                 // K chunks of 64
#define W_CHUNK_BYTES 32768      // 256 n-rows x 64 k x 2B (swizzled, 128B rows)
#define A_CHUNK_BYTES 8192       // 64 k-rows x 64 pix x 2B (swizzled, 128B rows)

// GEMM smem layout
#define SMG_A 0                               // 2 x 8192
#define SMG_W (2 * A_CHUNK_BYTES)             // 2 x 32768
#define SMEM_GEMM (SMG_W + 2 * W_CHUNK_BYTES) // 81920 B -> 2 CTAs/SM

#define PROJECT_BLOCKS ((NPTS + 255) / 256)   // 391
#define WCONV_BLOCKS   64

// ---------------- scratch (device globals: no allocation allowed) -------------
__device__ __align__(16) char g_Wbf16[C_PT * C_IMG * 2];    // bf16 W, chunked+swizzled
__device__ __align__(16) __half g_G[NPIX * C_PT];           // per-pixel aligned feat, 31.5 MB
__device__ float4 g_w[NPTS];
__device__ int4   g_off[NPTS];
__device__ int    g_tileflag[NTILE];          // 1 = tile referenced (zeroed by blend)

// ---------------- helpers ------------------------------------------------------
__device__ __forceinline__ uint32_t smem_u32(const void* p) {
    uint32_t a;
    asm("{ .reg .u64 t; cvta.to.shared.u64 t, %1; cvt.u32.u64 %0, t; }"
        : "=r"(a) : "l"(p));
    return a;
}

#define LDSM_X4(r0, r1, r2, r3, addr) \
    asm volatile("ldmatrix.sync.aligned.m8n8.x4.shared.b16 {%0,%1,%2,%3}, [%4];" \
                 : "=r"(r0), "=r"(r1), "=r"(r2), "=r"(r3) : "r"(addr))

#define LDSM_X4_T(r0, r1, r2, r3, addr) \
    asm volatile("ldmatrix.sync.aligned.m8n8.x4.trans.shared.b16 {%0,%1,%2,%3}, [%4];" \
                 : "=r"(r0), "=r"(r1), "=r"(r2), "=r"(r3) : "r"(addr))

__device__ __forceinline__ void mma_bf16(float* d, const uint32_t* a,
                                         uint32_t b0, uint32_t b1) {
    asm volatile(
        "mma.sync.aligned.m16n8k16.row.col.f32.bf16.bf16.f32 "
        "{%0,%1,%2,%3}, {%4,%5,%6,%7}, {%8,%9}, {%0,%1,%2,%3};"
        : "+f"(d[0]), "+f"(d[1]), "+f"(d[2]), "+f"(d[3])
        : "r"(a[0]), "r"(a[1]), "r"(a[2]), "r"(a[3]), "r"(b0), "r"(b1));
}

#define CP_ASYNC16(dst, src) \
    asm volatile("cp.async.cg.shared.global [%0], [%1], 16;" \
                 :: "r"(dst), "l"(src) : "memory")
#define CP_COMMIT() asm volatile("cp.async.commit_group;" ::: "memory")
#define CP_WAIT_ALL() asm volatile("cp.async.wait_group 0;" ::: "memory")

// ================== kernel 1: project points + convert W (merged) =============
__global__ void pre_kernel(const float* __restrict__ centers,
                           const int* __restrict__ bidx,
                           const float* __restrict__ P2,
                           const float* __restrict__ R0,
                           const float* __restrict__ Tr,
                           const float* __restrict__ aw) {
    const int t = threadIdx.x;
    if (blockIdx.x < PROJECT_BLOCKS) {
        // cooperative combined-matrix build: M[b] = P2[b] @ R0[b] @ Tr[b] (3x4)
        __shared__ float s_M[BSZ][12];
        if (t < BSZ * 12) {
            int b = t / 12;
            int i = (t % 12) >> 2;   // row 0..2
            int j = t & 3;           // col 0..3
            float s = 0.f;
            #pragma unroll
            for (int k = 0; k < 4; ++k) {
                // A[k][j] = sum_m R0[b][k][m] * Tr[b][m][j]
                float a = 0.f;
                #pragma unroll
                for (int m = 0; m < 4; ++m)
                    a += R0[b*16 + k*4 + m] * Tr[b*16 + m*4 + j];
                s += P2[b*12 + i*4 + k] * a;
            }
            s_M[b][i*4 + j] = s;
        }
        __syncthreads();

        int tid = blockIdx.x * 256 + t;
        if (tid >= NPTS) return;
        int b = bidx[tid];
        const float* M = s_M[b];
        float x = centers[tid * 3 + 0];
        float y = centers[tid * 3 + 1];
        float z = centers[tid * 3 + 2];
        float u  = M[0] * x + M[1] * y + M[2]  * z + M[3];
        float v  = M[4] * x + M[5] * y + M[6]  * z + M[7];
        float zc = M[8] * x + M[9] * y + M[10] * z + M[11];
        float depth = fmaxf(zc, 1e-5f);
        float uu = u / depth;
        float vv = v / depth;
        bool valid = (zc > 0.f) && (uu >= 0.f) && (uu < (float)IMW) &&
                     (vv >= 0.f) && (vv < (float)IMH);
        float x0f = floorf(uu), y0f = floorf(vv);
        float wx1 = uu - x0f, wx0 = 1.f - wx1;
        float wy1 = vv - y0f, wy0 = 1.f - wy1;
        int xi0 = (int)x0f, yi0 = (int)y0f;

        int   xs[4] = {xi0, xi0 + 1, xi0, xi0 + 1};
        int   ys[4] = {yi0, yi0, yi0 + 1, yi0 + 1};
        float ws[4] = {wx0 * wy0, wx1 * wy0, wx0 * wy1, wx1 * wy1};
        float wo[4];
        int   oo[4];
        #pragma unroll
        for (int j = 0; j < 4; ++j) {
            bool inb = (xs[j] >= 0) && (xs[j] <= IMW - 1) &&
                       (ys[j] >= 0) && (ys[j] <= IMH - 1);
            int xc = min(max(xs[j], 0), IMW - 1);
            int yc = min(max(ys[j], 0), IMH - 1);
            oo[j] = ((b * IMH + yc) * IMW + xc) * C_PT;   // offsets into G
            wo[j] = (valid && inb) ? ws[j] : 0.f;   // select, never multiply
        }
        g_w[tid]   = make_float4(wo[0], wo[1], wo[2], wo[3]);
        g_off[tid] = make_int4(oo[0], oo[1], oo[2], oo[3]);
        // mark referenced G tiles (idempotent plain stores; offsets are read
        // by blend_kernel regardless of weight, so flag all four)
        g_tileflag[oo[0] >> 14] = 1;
        g_tileflag[oo[1] >> 14] = 1;
        g_tileflag[oo[2] >> 14] = 1;
        g_tileflag[oo[3] >> 14] = 1;
    } else {
        // W: chunk c (32KB, K=64): n-row 128B = 8 16B-blocks,
        // block kb at byte c*32768 + n*128 + ((kb ^ (n&7)) << 4)
        int idx = (blockIdx.x - PROJECT_BLOCKS) * 256 + t;
        int n   = idx >> 6;
        int kbg = idx & 63;
        int c   = kbg >> 3;          // chunk 0..7
        int kb  = kbg & 7;           // block within chunk
        const float4* src = (const float4*)&aw[(size_t)n * C_IMG + kbg * 8];
        float4 v0 = src[0];
        float4 v1 = src[1];
        uint32_t u[4];
        __nv_bfloat162 t0 = __float22bfloat162_rn(make_float2(v0.x, v0.y));
        __nv_bfloat162 t1 = __float22bfloat162_rn(make_float2(v0.z, v0.w));
        __nv_bfloat162 t2 = __float22bfloat162_rn(make_float2(v1.x, v1.y));
        __nv_bfloat162 t3 = __float22bfloat162_rn(make_float2(v1.z, v1.w));
        u[0] = *(uint32_t*)&t0; u[1] = *(uint32_t*)&t1;
        u[2] = *(uint32_t*)&t2; u[3] = *(uint32_t*)&t3;
        *(int4*)(g_Wbf16 + c * W_CHUNK_BYTES + n * 128 + ((kb ^ (n & 7)) << 4)) =
            *(int4*)u;
    }
}

// ================== kernel 2: dense pixel GEMM  G = img^T @ W^T ===============
// A = img in native (B,C,H,W) layout, staged fp32->bf16 per K=64 chunk,
// ldmatrix.trans. 256 threads = 8 warps, warp grid 2(Mpix) x 4(Nch), tile 32x64.
// CTAs whose 64-pixel tile is never referenced by any point exit immediately.
__global__ void __launch_bounds__(256, 2)
gemm_kernel(const float* __restrict__ img) {
    if (g_tileflag[blockIdx.x] == 0) return;   // uniform early exit

    extern __shared__ char sm[];
    uint32_t smb = smem_u32(sm);

    const int t    = threadIdx.x;
    const int lane = t & 31;
    const int warp = t >> 5;
    const int p0   = blockIdx.x * TM;          // global pixel base
    const int b    = p0 / PIXB;                // batch (tiles never cross)
    const int hw0  = p0 % PIXB;

    // A staging: thread owns k-rows (kl, kl+32), pixel block px8 (8 px = 16B bf16)
    const int kl   = t >> 3;          // 0..31
    const int px8  = (t & 7) * 8;
    const float* imgb = img + ((size_t)b * C_IMG) * PIXB + hw0 + px8;
    const uint32_t asts0 = smb + SMG_A + kl * 128 +
                           ((((unsigned)px8 >> 3) ^ (kl & 7)) << 4);
    const uint32_t asts1 = asts0 + 32 * 128;   // (kl+32)&7 == kl&7

    // ---- prologue: stage img chunk 0, prefetch W chunk 0 -----------------------
    {
        const float* s0 = imgb + (size_t)kl * PIXB;
        const float* s1 = imgb + (size_t)(kl + 32) * PIXB;
        float4 v0 = *(const float4*)(s0);
        float4 v1 = *(const float4*)(s0 + 4);
        float4 v2 = *(const float4*)(s1);
        float4 v3 = *(const float4*)(s1 + 4);
        __nv_bfloat162 h0 = __float22bfloat162_rn(make_float2(v0.x, v0.y));
        __nv_bfloat162 h1 = __float22bfloat162_rn(make_float2(v0.z, v0.w));
        __nv_bfloat162 h2 = __float22bfloat162_rn(make_float2(v1.x, v1.y));
        __nv_bfloat162 h3 = __float22bfloat162_rn(make_float2(v1.z, v1.w));
        __nv_bfloat162 h4 = __float22bfloat162_rn(make_float2(v2.x, v2.y));
        __nv_bfloat162 h5 = __float22bfloat162_rn(make_float2(v2.z, v2.w));
        __nv_bfloat162 h6 = __float22bfloat162_rn(make_float2(v3.x, v3.y));
        __nv_bfloat162 h7 = __float22bfloat162_rn(make_float2(v3.z, v3.w));
        asm volatile("st.shared.v4.b32 [%0], {%1, %2, %3, %4};"
                     :: "r"(asts0), "r"(*(uint32_t*)&h0), "r"(*(uint32_t*)&h1),
                        "r"(*(uint32_t*)&h2), "r"(*(uint32_t*)&h3));
        asm volatile("st.shared.v4.b32 [%0], {%1, %2, %3, %4};"
                     :: "r"(asts1), "r"(*(uint32_t*)&h4), "r"(*(uint32_t*)&h5),
                        "r"(*(uint32_t*)&h6), "r"(*(uint32_t*)&h7));
    }
    {
        const char* src = g_Wbf16;
        uint32_t dst = smb + SMG_W;
        #pragma unroll
        for (int j = 0; j < 8; ++j)
            CP_ASYNC16(dst + (t + j * 256) * 16, src + (size_t)(t + j * 256) * 16);
        CP_COMMIT();
    }

    const int wm = warp & 1;    // pixel group (32 rows)
    const int wn = warp >> 1;   // channel group (64 cols)
    float acc[2][8][4];
    #pragma unroll
    for (int i = 0; i < 2; ++i)
        #pragma unroll
        for (int j = 0; j < 8; ++j)
            #pragma unroll
            for (int r = 0; r < 4; ++r) acc[i][j][r] = 0.f;

    // A (trans) lane addressing
    const int krow  = (lane & 7) | ((lane >> 4) << 3);
    const int mhalf = (lane >> 3) & 1;
    const uint32_t ablk0 = ((unsigned)((wm * 32) >> 3) + mhalf) ^ (lane & 7);
    const uint32_t ablk1 = ((unsigned)((wm * 32 + 16) >> 3) + mhalf) ^ (lane & 7);
    const uint32_t abase0 = krow * 128 + (ablk0 << 4);
    const uint32_t abase1 = krow * 128 + (ablk1 << 4);
    // B (W) lane addressing (128B rows, swizzle kb ^ (n&7) — proven in R3)
    const int brow  = wn * 64 + (lane >> 4) * 8 + (lane & 7);
    const int bhalf = (lane >> 3) & 1;

    CP_WAIT_ALL();
    __syncthreads();

    for (int c = 0; c < NCHUNK; ++c) {
        float4 v0, v1, v2, v3;
        if (c + 1 < NCHUNK) {
            // prefetch img chunk c+1 (4 independent LDG.128)
            const float* s0 = imgb + (size_t)((c + 1) * 64 + kl) * PIXB;
            const float* s1 = imgb + (size_t)((c + 1) * 64 + kl + 32) * PIXB;
            v0 = *(const float4*)(s0);
            v1 = *(const float4*)(s0 + 4);
            v2 = *(const float4*)(s1);
            v3 = *(const float4*)(s1 + 4);
            // prefetch W chunk c+1
            const char* src = g_Wbf16 + (size_t)(c + 1) * W_CHUNK_BYTES;
            uint32_t dst = smb + SMG_W + ((c + 1) & 1) * W_CHUNK_BYTES;
            #pragma unroll
            for (int j = 0; j < 8; ++j)
                CP_ASYNC16(dst + (t + j * 256) * 16, src + (size_t)(t + j * 256) * 16);
            CP_COMMIT();
        }
        const uint32_t abuf = smb + SMG_A + (c & 1) * A_CHUNK_BYTES;
        const uint32_t wbuf = smb + SMG_W + (c & 1) * W_CHUNK_BYTES;

        #pragma unroll
        for (int ks = 0; ks < 4; ++ks) {
            uint32_t a[2][4];
            LDSM_X4_T(a[0][0], a[0][1], a[0][2], a[0][3],
                      abuf + ks * 2048 + abase0);
            LDSM_X4_T(a[1][0], a[1][1], a[1][2], a[1][3],
                      abuf + ks * 2048 + abase1);
            #pragma unroll
            for (int jj = 0; jj < 4; ++jj) {
                uint32_t b0, b1, b2, b3;
                int nrow = brow + jj * 16;
                int kb   = (ks * 2 + bhalf) ^ (nrow & 7);
                LDSM_X4(b0, b1, b2, b3, wbuf + nrow * 128 + (kb << 4));
                mma_bf16(acc[0][2 * jj],     a[0], b0, b1);
                mma_bf16(acc[0][2 * jj + 1], a[0], b2, b3);
                mma_bf16(acc[1][2 * jj],     a[1], b0, b1);
                mma_bf16(acc[1][2 * jj + 1], a[1], b2, b3);
            }
        }

        if (c + 1 < NCHUNK) {
            // convert + store img chunk c+1 into the other A buffer
            __nv_bfloat162 h0 = __float22bfloat162_rn(make_float2(v0.x, v0.y));
            __nv_bfloat162 h1 = __float22bfloat162_rn(make_float2(v0.z, v0.w));
            __nv_bfloat162 h2 = __float22bfloat162_rn(make_float2(v1.x, v1.y));
            __nv_bfloat162 h3 = __float22bfloat162_rn(make_float2(v1.z, v1.w));
            __nv_bfloat162 h4 = __float22bfloat162_rn(make_float2(v2.x, v2.y));
            __nv_bfloat162 h5 = __float22bfloat162_rn(make_float2(v2.z, v2.w));
            __nv_bfloat162 h6 = __float22bfloat162_rn(make_float2(v3.x, v3.y));
            __nv_bfloat162 h7 = __float22bfloat162_rn(make_float2(v3.z, v3.w));
            uint32_t off = (((c + 1) & 1) ? A_CHUNK_BYTES : 0);
            asm volatile("st.shared.v4.b32 [%0], {%1, %2, %3, %4};"
                         :: "r"(asts0 + off), "r"(*(uint32_t*)&h0), "r"(*(uint32_t*)&h1),
                            "r"(*(uint32_t*)&h2), "r"(*(uint32_t*)&h3));
            asm volatile("st.shared.v4.b32 [%0], {%1, %2, %3, %4};"
                         :: "r"(asts1 + off), "r"(*(uint32_t*)&h4), "r"(*(uint32_t*)&h5),
                            "r"(*(uint32_t*)&h6), "r"(*(uint32_t*)&h7));
            CP_WAIT_ALL();
            __syncthreads();
        }
    }

    // ---- epilogue: G[pixel][col] = acc (fp16) -----------------------------------
    const int cbase = wn * 64 + (lane & 3) * 2;
    const int rbase = p0 + wm * 32 + (lane >> 2);
    #pragma unroll
    for (int i = 0; i < 2; ++i) {
        #pragma unroll
        for (int half = 0; half < 2; ++half) {
            int pix = rbase + i * 16 + half * 8;
            #pragma unroll
            for (int j = 0; j < 8; ++j) {
                int col = cbase + j * 8;
                __half2 h = __floats2half2_rn(acc[i][j][half * 2 + 0],
                                              acc[i][j][half * 2 + 1]);
                *(__half2*)&g_G[(size_t)pix * C_PT + col] = h;
            }
        }
    }
}

// ================== kernel 3: per-point blend + residual ======================
// 1 warp per 2 points; lane owns 8 channels. Also zeroes tile flags for the
// next launch (gemm consumed them earlier in this launch; device globals are
// zero-initialized, so the first call is covered too).
__global__ void __launch_bounds__(256)
blend_kernel(const float* __restrict__ point_feat,
             const float* __restrict__ align_b,
             float* __restrict__ out) {
    // reset tile flags (blocks 0..3 cover NTILE=960 ints)
    if (blockIdx.x < 4) {
        int i = blockIdx.x * 256 + threadIdx.x;
        if (i < NTILE) g_tileflag[i] = 0;
    }

    const int lane = threadIdx.x & 31;
    const int p    = blockIdx.x * 16 + (threadIdx.x >> 5) * 2;
    const int ch   = lane * 8;

    float4 w0 = g_w[p];
    float4 w1 = g_w[p + 1];
    int4   o0 = g_off[p];
    int4   o1 = g_off[p + 1];
    // 8 independent G loads in flight (L2-only; no L1 reuse)
    uint4 a0 = __ldcg((const uint4*)(g_G + o0.x + ch));
    uint4 a1 = __ldcg((const uint4*)(g_G + o0.y + ch));
    uint4 a2 = __ldcg((const uint4*)(g_G + o0.z + ch));
    uint4 a3 = __ldcg((const uint4*)(g_G + o0.w + ch));
    uint4 b0 = __ldcg((const uint4*)(g_G + o1.x + ch));
    uint4 b1 = __ldcg((const uint4*)(g_G + o1.y + ch));
    uint4 b2 = __ldcg((const uint4*)(g_G + o1.z + ch));
    uint4 b3 = __ldcg((const uint4*)(g_G + o1.w + ch));

    float4 bias0 = *(const float4*)&align_b[ch];
    float4 bias1 = *(const float4*)&align_b[ch + 4];

    #pragma unroll
    for (int pt = 0; pt < 2; ++pt) {
        float4 w = pt ? w1 : w0;
        uint4 c0 = pt ? b0 : a0;
        uint4 c1 = pt ? b1 : a1;
        uint4 c2 = pt ? b2 : a2;
        uint4 c3 = pt ? b3 : a3;
        float acc[8];
        #pragma unroll
        for (int k = 0; k < 4; ++k) {
            float2 f0 = __half22float2(((const __half2*)&c0)[k]);
            float2 f1 = __half22float2(((const __half2*)&c1)[k]);
            float2 f2 = __half22float2(((const __half2*)&c2)[k]);
            float2 f3 = __half22float2(((const __half2*)&c3)[k]);
            acc[2*k+0] = w.x * f0.x + w.y * f1.x + w.z * f2.x + w.w * f3.x;
            acc[2*k+1] = w.x * f0.y + w.y * f1.y + w.z * f2.y + w.w * f3.y;
        }
        const int pp = p + pt;
        const float4* pf = (const float4*)&point_feat[(size_t)pp * C_PT + ch];
        float4* op = (float4*)&out[(size_t)pp * C_PT + ch];
        float4 pa = __ldcs(pf);
        float4 pb = __ldcs(pf + 1);
        float4 r0, r1;
        r0.x = pa.x + bias0.x + acc[0];
        r0.y = pa.y + bias0.y + acc[1];
        r0.z = pa.z + bias0.z + acc[2];
        r0.w = pa.w + bias0.w + acc[3];
        r1.x = pb.x + bias1.x + acc[4];
        r1.y = pb.y + bias1.y + acc[5];
        r1.z = pb.z + bias1.z + acc[6];
        r1.w = pb.w + bias1.w + acc[7];
        __stcs(op, r0);
        __stcs(op + 1, r1);
    }
}

// ================== launcher ==================================================
extern "C" void kernel_launch(void* const* d_in, const int* in_sizes, int n_in,
                              void* d_out, int out_size) {
    const float* point_feat = (const float*)d_in[0];
    const float* centers    = (const float*)d_in[1];
    const float* img        = (const float*)d_in[2];
    const float* P2         = (const float*)d_in[3];
    const float* R0         = (const float*)d_in[4];
    const float* Tr         = (const float*)d_in[5];
    const float* align_w    = (const float*)d_in[6];
    const float* align_b    = (const float*)d_in[7];
    const int*   bidx       = (const int*)d_in[8];
    float* out = (float*)d_out;

    pre_kernel<<<PROJECT_BLOCKS + WCONV_BLOCKS, 256>>>(centers, bidx, P2, R0, Tr,
                                                       align_w);
    cudaFuncSetAttribute(gemm_kernel,
                         cudaFuncAttributeMaxDynamicSharedMemorySize, SMEM_GEMM);
    gemm_kernel<<<NTILE, 256, SMEM_GEMM>>>(img);
    blend_kernel<<<NPTS / 16, 256>>>(point_feat, align_b, out);
}